// round 14
// baseline (speedup 1.0000x reference)
#include <cuda_runtime.h>
#include <cuda_bf16.h>
#include <cstdint>

#define N0_   500000
#define N1_   100000
#define N2_   25000
#define E0_   1600000
#define E1_   400000
#define D_IN_ 128
#define D_H_  256
#define D_OUT_ 128

#define PAD0_ 102400
#define TOT_  128000
#define SBLK_ 125

// ---- scratch (allocation-free rule: __device__ globals) ----
__device__ float g_h[(size_t)N1_ * D_H_];
__device__ int g_deg[TOT_];
__device__ int g_scan[TOT_];
__device__ int g_bsum[SBLK_];
__device__ int g_off[TOT_];
__device__ int g_wcur[TOT_];
__device__ int g_csr0[E0_];
__device__ int g_csr1[E1_];
__device__ __align__(128) __nv_bfloat16 g_A1h[(size_t)N1_ * 256];
__device__ __align__(128) __nv_bfloat16 g_A1l[(size_t)N1_ * 256];
__device__ __align__(128) __nv_bfloat16 g_A2h[(size_t)N2_ * 512];
__device__ __align__(128) __nv_bfloat16 g_A2l[(size_t)N2_ * 512];
__device__ __align__(128) __nv_bfloat16 g_B1h[256 * 256];
__device__ __align__(128) __nv_bfloat16 g_B1l[256 * 256];
__device__ __align__(128) __nv_bfloat16 g_B2h[128 * 512];
__device__ __align__(128) __nv_bfloat16 g_B2l[128 * 512];

// ---------------- ptx helpers (compute_103-safe) ----------------
__device__ __forceinline__ uint32_t smem_u32(const void* p) {
    uint32_t a;
    asm("{ .reg .u64 t; cvta.to.shared.u64 t, %1; cvt.u32.u64 %0, t; }" : "=r"(a) : "l"(p));
    return a;
}
__device__ __forceinline__ uint32_t sw128(uint32_t off) {
    return off ^ ((off >> 3) & 0x70);
}
__device__ __forceinline__ void cp16(uint32_t dst, const void* src, bool pred) {
    int sz = pred ? 16 : 0;
    asm volatile("cp.async.cg.shared.global [%0], [%1], 16, %2;"
                 :: "r"(dst), "l"(src), "r"(sz) : "memory");
}
__device__ __forceinline__ void ldsm4(uint32_t& r0, uint32_t& r1, uint32_t& r2, uint32_t& r3,
                                      uint32_t addr) {
    asm volatile("ldmatrix.sync.aligned.m8n8.x4.shared.b16 {%0,%1,%2,%3}, [%4];"
                 : "=r"(r0), "=r"(r1), "=r"(r2), "=r"(r3) : "r"(addr));
}
__device__ __forceinline__ void mma16816(float* c, uint32_t a0, uint32_t a1, uint32_t a2,
                                         uint32_t a3, uint32_t b0, uint32_t b1) {
    asm volatile(
        "mma.sync.aligned.m16n8k16.row.col.f32.bf16.bf16.f32 "
        "{%0,%1,%2,%3}, {%4,%5,%6,%7}, {%8,%9}, {%0,%1,%2,%3};"
        : "+f"(c[0]), "+f"(c[1]), "+f"(c[2]), "+f"(c[3])
        : "r"(a0), "r"(a1), "r"(a2), "r"(a3), "r"(b0), "r"(b1));
}
__device__ __forceinline__ uint32_t pack_bf16x2(float a, float b) {
    __nv_bfloat162 p = __floats2bfloat162_rn(a, b);
    return *(uint32_t*)&p;
}
__device__ __forceinline__ void split_store(__nv_bfloat16* hi, __nv_bfloat16* lo,
                                            size_t o, float4 v) {
    float hx = __bfloat162float(__float2bfloat16(v.x));
    float hy = __bfloat162float(__float2bfloat16(v.y));
    float hz = __bfloat162float(__float2bfloat16(v.z));
    float hw = __bfloat162float(__float2bfloat16(v.w));
    uint2 ph = make_uint2(pack_bf16x2(hx, hy), pack_bf16x2(hz, hw));
    uint2 pl = make_uint2(pack_bf16x2(v.x - hx, v.y - hy),
                          pack_bf16x2(v.z - hz, v.w - hw));
    *(uint2*)(hi + o) = ph;
    *(uint2*)(lo + o) = pl;
}

// ---------------- prep: zero degree array + split both weight matrices ----------------
__global__ void prep_kernel(int4* deg,
                            const float* __restrict__ Wl0, const float* __restrict__ Wr0,
                            const float* __restrict__ Wl1, const float* __restrict__ Wr1,
                            __nv_bfloat16* __restrict__ B1h, __nv_bfloat16* __restrict__ B1l,
                            __nv_bfloat16* __restrict__ B2h, __nv_bfloat16* __restrict__ B2l) {
    const int Z = TOT_ / 4;
    const int T1 = 256 * (256 / 4);
    const int T2 = 128 * (512 / 4);
    int i = blockIdx.x * blockDim.x + threadIdx.x;
    if (i < Z) {
        deg[i] = make_int4(0, 0, 0, 0);
    } else if (i < Z + T1) {
        int k = i - Z;
        int row = k / 64;
        int c4 = (k % 64) * 4;
        float4 v = (c4 < 128) ? *(const float4*)(Wl0 + (size_t)row * 128 + c4)
                              : *(const float4*)(Wr0 + (size_t)row * 128 + (c4 - 128));
        split_store(B1h, B1l, (size_t)row * 256 + c4, v);
    } else if (i < Z + T1 + T2) {
        int k = i - Z - T1;
        int row = k / 128;
        int c4 = (k % 128) * 4;
        float4 v = (c4 < 256) ? *(const float4*)(Wl1 + (size_t)row * 256 + c4)
                              : *(const float4*)(Wr1 + (size_t)row * 256 + (c4 - 256));
        split_store(B2h, B2l, (size_t)row * 512 + c4, v);
    }
}

// ---------------- CSR build kernels ----------------
__global__ void hist_deg(const int* __restrict__ d0, const int* __restrict__ d1,
                         int* __restrict__ deg) {
    int i = blockIdx.x * blockDim.x + threadIdx.x;
    if (i < E0_) atomicAdd(&deg[d0[i]], 1);
    else if (i < E0_ + E1_) atomicAdd(&deg[PAD0_ + d1[i - E0_]], 1);
}

__global__ void __launch_bounds__(1024) scan_part(const int* __restrict__ deg,
                                                  int* __restrict__ scn,
                                                  int* __restrict__ bsum) {
    __shared__ int sm[1024];
    int t = threadIdx.x;
    int gid = blockIdx.x * 1024 + t;
    sm[t] = deg[gid];
    __syncthreads();
    #pragma unroll
    for (int o = 1; o < 1024; o <<= 1) {
        int u = (t >= o) ? sm[t - o] : 0;
        __syncthreads();
        sm[t] += u;
        __syncthreads();
    }
    scn[gid] = sm[t];
    if (t == 1023) bsum[blockIdx.x] = sm[t];
}

// scan_add with block-sum prefix folded in (each CTA reduces bsum[0..b-1] itself)
__global__ void scan_add(const int* __restrict__ scn, const int* __restrict__ deg,
                         const int* __restrict__ bsum,
                         int* __restrict__ off, int* __restrict__ wcur) {
    __shared__ int sbase;
    int b = (blockIdx.x * 256) >> 10;   // uniform per CTA (256 divides 1024)
    if (threadIdx.x == 0) sbase = 0;
    __syncthreads();
    if (threadIdx.x < b) atomicAdd(&sbase, bsum[threadIdx.x]);
    __syncthreads();
    int gid = blockIdx.x * 256 + threadIdx.x;
    int incl = scn[gid] + sbase;
    int start = incl - deg[gid];
    if (gid >= PAD0_) start -= E0_;
    off[gid] = start;
    wcur[gid] = start;
}

__global__ void fill_csr(const int* __restrict__ s0, const int* __restrict__ d0,
                         const int* __restrict__ s1, const int* __restrict__ d1,
                         int* __restrict__ wcur,
                         int* __restrict__ csr0, int* __restrict__ csr1) {
    int i = blockIdx.x * blockDim.x + threadIdx.x;
    if (i < E0_) {
        int pos = atomicAdd(&wcur[d0[i]], 1);
        csr0[pos] = s0[i];
    } else if (i < E0_ + E1_) {
        int j = i - E0_;
        int pos = atomicAdd(&wcur[PAD0_ + d1[j]], 1);
        csr1[pos] = s1[j];
    }
}

// ---------------- atomic-free gather + mean + bf16 split ----------------
__global__ void __launch_bounds__(256) gather0(const float* __restrict__ x,
                                               const int* __restrict__ off,
                                               const int* __restrict__ csr,
                                               __nv_bfloat16* __restrict__ hi,
                                               __nv_bfloat16* __restrict__ lo) {
    int row = (blockIdx.x * blockDim.x + threadIdx.x) >> 5;
    int lane = threadIdx.x & 31;
    if (row >= N1_) return;
    int start = off[row];
    int deg = off[row + 1] - start;

    float4 acc = make_float4(0.f, 0.f, 0.f, 0.f);
    for (int base = 0; base < deg; base += 32) {
        int idx = 0;
        if (base + lane < deg) idx = __ldg(csr + start + base + lane);
        int nn = min(32, deg - base);
        #pragma unroll 4
        for (int j = 0; j < nn; j++) {
            int s = __shfl_sync(0xffffffffu, idx, j);
            float4 v = __ldg((const float4*)(x + (size_t)s * D_IN_) + lane);
            acc.x += v.x; acc.y += v.y; acc.z += v.z; acc.w += v.w;
        }
    }
    float inv = 1.0f / fmaxf((float)deg, 1.0f);
    acc.x *= inv; acc.y *= inv; acc.z *= inv; acc.w *= inv;
    size_t ro = (size_t)row * 256 + lane * 4;
    split_store(hi, lo, ro, acc);
    float4 xr = __ldg((const float4*)(x + (size_t)row * D_IN_) + lane);
    split_store(hi, lo, ro + 128, xr);
}

__global__ void __launch_bounds__(256) gather1(const float* __restrict__ h,
                                               const int* __restrict__ off,
                                               const int* __restrict__ csr,
                                               __nv_bfloat16* __restrict__ hi,
                                               __nv_bfloat16* __restrict__ lo) {
    int row = (blockIdx.x * blockDim.x + threadIdx.x) >> 5;
    int lane = threadIdx.x & 31;
    if (row >= N2_) return;
    int start = off[PAD0_ + row];
    int deg = off[PAD0_ + row + 1] - start;

    float4 a0 = make_float4(0.f, 0.f, 0.f, 0.f);
    float4 a1 = make_float4(0.f, 0.f, 0.f, 0.f);
    for (int base = 0; base < deg; base += 32) {
        int idx = 0;
        if (base + lane < deg) idx = __ldg(csr + start + base + lane);
        int nn = min(32, deg - base);
        #pragma unroll 2
        for (int j = 0; j < nn; j++) {
            int s = __shfl_sync(0xffffffffu, idx, j);
            const float4* hr = (const float4*)(h + (size_t)s * D_H_);
            float4 v0 = __ldg(hr + lane);
            float4 v1 = __ldg(hr + 32 + lane);
            a0.x += v0.x; a0.y += v0.y; a0.z += v0.z; a0.w += v0.w;
            a1.x += v1.x; a1.y += v1.y; a1.z += v1.z; a1.w += v1.w;
        }
    }
    float inv = 1.0f / fmaxf((float)deg, 1.0f);
    a0.x *= inv; a0.y *= inv; a0.z *= inv; a0.w *= inv;
    a1.x *= inv; a1.y *= inv; a1.z *= inv; a1.w *= inv;
    size_t ro = (size_t)row * 512 + lane * 4;
    split_store(hi, lo, ro, a0);
    split_store(hi, lo, ro + 128, a1);
}

// ---------------- mma.sync bf16 GEMM: fused-B phases, 2-stage, 2 CTAs/SM ----------------
// Phase A (NCP chunks): stage holds {Ah, Bh, Bl}; computes Ah*Bh + Ah*Bl.
// Phase B (NCP chunks): stage holds {Al, Bh};     computes Al*Bh.
// grid = (N/128, ceil(M/MTILE)); 8 warps 2(M) x 4(N); warp tile (MTILE/2) x 32.
template<int K, int MTILE, bool RELU, bool WSPLIT>
__global__ void __launch_bounds__(256, 2)
gemm_mma(const __nv_bfloat16* __restrict__ Ah, const __nv_bfloat16* __restrict__ Al,
         const __nv_bfloat16* __restrict__ Bh, const __nv_bfloat16* __restrict__ Bl,
         const float* __restrict__ bias, float* __restrict__ C, int M, int Nstride,
         __nv_bfloat16* __restrict__ A2h, __nv_bfloat16* __restrict__ A2l, int n2) {
    constexpr int NCP = K / 64;
    constexpr int NSTEP = 2 * NCP;
    constexpr int ATILE = MTILE * 128;
    constexpr int BT = 128 * 128;            // 16 KB per B tile
    constexpr int STILE = ATILE + 2 * BT;
    constexpr int MT = MTILE / 32;
    constexpr int NT = 4;
    constexpr int AG = MTILE * 8;            // A cp granules

    extern __shared__ char dsm[];
    char* tb = (char*)((((uintptr_t)dsm) + 1023) & ~(uintptr_t)1023);
    uint32_t aBase[2], b0Base[2], b1Base[2];
    #pragma unroll
    for (int s = 0; s < 2; s++) {
        aBase[s]  = smem_u32(tb + s * STILE);
        b0Base[s] = smem_u32(tb + s * STILE + ATILE);
        b1Base[s] = smem_u32(tb + s * STILE + ATILE + BT);
    }

    const int tid  = threadIdx.x;
    const int wid  = tid >> 5;
    const int lane = tid & 31;
    const int bn0  = blockIdx.x * 128;
    const int m0   = blockIdx.y * MTILE;
    const int wm0  = (wid >> 2) * (MTILE / 2);
    const int wn0  = (wid & 3) * 32;

    float acc[MT][NT][4];
    #pragma unroll
    for (int i = 0; i < MT; i++)
        #pragma unroll
        for (int j = 0; j < NT; j++)
            #pragma unroll
            for (int e = 0; e < 4; e++) acc[i][j][e] = 0.f;

    auto load_chunk = [&](int step, int buf) {
        const bool dual = step < NCP;
        const int kc = (step % NCP) * 64;
        const __nv_bfloat16* As = dual ? Ah : Al;
        const int glim = AG + (dual ? 2048 : 1024);
        for (int g = tid; g < glim; g += 256) {
            if (g < AG) {
                int row = g >> 3, c = g & 7;
                int gr = m0 + row;
                bool ok = gr < M;
                int grs = ok ? gr : (M - 1);
                cp16(aBase[buf] + sw128((uint32_t)(row * 128 + c * 16)),
                     As + (size_t)grs * K + kc + c * 8, ok);
            } else if (g < AG + 1024) {
                int g2 = g - AG;
                int row = g2 >> 3, c = g2 & 7;
                cp16(b0Base[buf] + sw128((uint32_t)(row * 128 + c * 16)),
                     Bh + (size_t)(bn0 + row) * K + kc + c * 8, true);
            } else {
                int g2 = g - AG - 1024;
                int row = g2 >> 3, c = g2 & 7;
                cp16(b1Base[buf] + sw128((uint32_t)(row * 128 + c * 16)),
                     Bl + (size_t)(bn0 + row) * K + kc + c * 8, true);
            }
        }
        asm volatile("cp.async.commit_group;" ::: "memory");
    };

    load_chunk(0, 0);

    for (int step = 0; step < NSTEP; step++) {
        const int buf = step & 1;
        if (step + 1 < NSTEP) {
            load_chunk(step + 1, buf ^ 1);
            asm volatile("cp.async.wait_group 1;" ::: "memory");
        } else {
            asm volatile("cp.async.wait_group 0;" ::: "memory");
        }
        __syncthreads();

        const bool dual = step < NCP;
        const uint32_t aB = aBase[buf];
        const uint32_t b0B = b0Base[buf];
        const uint32_t b1B = b1Base[buf];
        #pragma unroll
        for (int ks = 0; ks < 4; ks++) {
            const int kb = ks * 32;
            uint32_t b0f[NT][2], b1f[NT][2];
            #pragma unroll
            for (int nt2 = 0; nt2 < NT / 2; nt2++) {
                int n0 = wn0 + nt2 * 16;
                int rsel = (lane & 7) + ((lane >> 4) << 3);
                int ksel = (lane >> 3) & 1;
                uint32_t off = (uint32_t)((n0 + rsel) * 128 + kb + ksel * 16);
                ldsm4(b0f[2 * nt2][0], b0f[2 * nt2][1],
                      b0f[2 * nt2 + 1][0], b0f[2 * nt2 + 1][1], b0B + sw128(off));
                if (dual)
                    ldsm4(b1f[2 * nt2][0], b1f[2 * nt2][1],
                          b1f[2 * nt2 + 1][0], b1f[2 * nt2 + 1][1], b1B + sw128(off));
            }
            #pragma unroll
            for (int mt = 0; mt < MT; mt++) {
                int mrow = wm0 + mt * 16;
                int rsel = (lane & 7) + (((lane >> 3) & 1) << 3);
                int ksel = lane >> 4;
                uint32_t off = (uint32_t)((mrow + rsel) * 128 + kb + ksel * 16);
                uint32_t a0, a1, a2, a3;
                ldsm4(a0, a1, a2, a3, aB + sw128(off));
                #pragma unroll
                for (int nt = 0; nt < NT; nt++) {
                    mma16816(acc[mt][nt], a0, a1, a2, a3, b0f[nt][0], b0f[nt][1]);
                    if (dual)
                        mma16816(acc[mt][nt], a0, a1, a2, a3, b1f[nt][0], b1f[nt][1]);
                }
            }
        }
        __syncthreads();   // protect buf from next iteration's cp.async overwrite
    }

    // epilogue
    #pragma unroll
    for (int mt = 0; mt < MT; mt++) {
        int rr[2];
        rr[0] = m0 + wm0 + mt * 16 + (lane >> 2);
        rr[1] = rr[0] + 8;
        #pragma unroll
        for (int nt = 0; nt < NT; nt++) {
            int c = bn0 + wn0 + nt * 8 + (lane & 3) * 2;
            float2 bv = *(const float2*)(bias + c);
            #pragma unroll
            for (int half = 0; half < 2; half++) {
                int r = rr[half];
                if (r < M) {
                    float2 v = make_float2(acc[mt][nt][2 * half + 0] + bv.x,
                                           acc[mt][nt][2 * half + 1] + bv.y);
                    if (RELU) { v.x = fmaxf(v.x, 0.f); v.y = fmaxf(v.y, 0.f); }
                    *(float2*)(C + (size_t)r * Nstride + c) = v;
                    if (WSPLIT && r < n2) {
                        float hx = __bfloat162float(__float2bfloat16(v.x));
                        float hy = __bfloat162float(__float2bfloat16(v.y));
                        size_t o = (size_t)r * 512 + 256 + c;
                        *(uint32_t*)(A2h + o) = pack_bf16x2(hx, hy);
                        *(uint32_t*)(A2l + o) = pack_bf16x2(v.x - hx, v.y - hy);
                    }
                }
            }
        }
    }
}

// ---------------- host side ----------------
extern "C" void kernel_launch(void* const* d_in, const int* in_sizes, int n_in,
                              void* d_out, int out_size) {
    const float* x   = (const float*)d_in[0];
    const float* Wl0 = (const float*)d_in[1];
    const float* bl0 = (const float*)d_in[2];
    const float* Wr0 = (const float*)d_in[3];
    const float* Wl1 = (const float*)d_in[4];
    const float* bl1 = (const float*)d_in[5];
    const float* Wr1 = (const float*)d_in[6];
    const int* e0s = (const int*)d_in[7];
    const int* e0d = (const int*)d_in[8];
    const int* e1s = (const int*)d_in[9];
    const int* e1d = (const int*)d_in[10];
    float* out = (float*)d_out;

    float* h;
    int *deg, *scn, *bsum, *off, *wcur, *csr0, *csr1;
    __nv_bfloat16 *A1h, *A1l, *A2h, *A2l, *B1h, *B1l, *B2h, *B2l;
    cudaGetSymbolAddress((void**)&h,    g_h);
    cudaGetSymbolAddress((void**)&deg,  g_deg);
    cudaGetSymbolAddress((void**)&scn,  g_scan);
    cudaGetSymbolAddress((void**)&bsum, g_bsum);
    cudaGetSymbolAddress((void**)&off,  g_off);
    cudaGetSymbolAddress((void**)&wcur, g_wcur);
    cudaGetSymbolAddress((void**)&csr0, g_csr0);
    cudaGetSymbolAddress((void**)&csr1, g_csr1);
    cudaGetSymbolAddress((void**)&A1h, g_A1h);
    cudaGetSymbolAddress((void**)&A1l, g_A1l);
    cudaGetSymbolAddress((void**)&A2h, g_A2h);
    cudaGetSymbolAddress((void**)&A2l, g_A2l);
    cudaGetSymbolAddress((void**)&B1h, g_B1h);
    cudaGetSymbolAddress((void**)&B1l, g_B1l);
    cudaGetSymbolAddress((void**)&B2h, g_B2h);
    cudaGetSymbolAddress((void**)&B2l, g_B2l);

    const int smem1 = 1024 + 2 * (128 * 128 + 2 * 128 * 128);  // 99328
    const int smem2 = 1024 + 2 * (64 * 128 + 2 * 128 * 128);   // 82944
    cudaFuncSetAttribute(gemm_mma<256, 128, true, true>,
                         cudaFuncAttributeMaxDynamicSharedMemorySize, smem1);
    cudaFuncSetAttribute(gemm_mma<512, 64, false, false>,
                         cudaFuncAttributeMaxDynamicSharedMemorySize, smem2);

    const int ET = E0_ + E1_;

    // prep: zero deg + weight splits (one launch)
    {
        int tot = TOT_ / 4 + 256 * 64 + 128 * 128;
        prep_kernel<<<(tot + 255) / 256, 256>>>((int4*)deg, Wl0, Wr0, Wl1, Wr1,
                                                B1h, B1l, B2h, B2l);
    }
    // CSR build (scan_top folded into scan_add)
    hist_deg<<<(ET + 255) / 256, 256>>>(e0d, e1d, deg);
    scan_part<<<SBLK_, 1024>>>(deg, scn, bsum);
    scan_add<<<TOT_ / 256, 256>>>(scn, deg, bsum, off, wcur);
    fill_csr<<<(ET + 255) / 256, 256>>>(e0s, e0d, e1s, e1d, wcur, csr0, csr1);

    // hop 0: gather + mean + split -> A1 (both halves)
    gather0<<<(N1_ * 32 + 255) / 256, 256>>>(x, off, csr0, A1h, A1l);

    // h = relu(A1 @ B1^T + bl0); epilogue emits A2 right half (h[:N2])
    {
        dim3 grid(2, (N1_ + 127) / 128);
        gemm_mma<256, 128, true, true><<<grid, 256, smem1>>>(
            A1h, A1l, B1h, B1l, bl0, h, N1_, 256, A2h, A2l, N2_);
    }

    // hop 1: gather + mean + split -> A2 left half
    gather1<<<(N2_ * 32 + 255) / 256, 256>>>(h, off, csr1, A2h, A2l);

    // out = A2 @ B2^T + bl1
    {
        dim3 grid(1, (N2_ + 63) / 64);
        gemm_mma<512, 64, false, false><<<grid, 256, smem2>>>(
            A2h, A2l, B2h, B2l, bl1, out, N2_, 128, (__nv_bfloat16*)nullptr,
            (__nv_bfloat16*)nullptr, 0);
    }
}

// round 15
// speedup vs baseline: 1.1159x; 1.1159x over previous
#include <cuda_runtime.h>
#include <cuda_bf16.h>
#include <cstdint>

#define N0_   500000
#define N1_   100000
#define N2_   25000
#define E0_   1600000
#define E1_   400000
#define D_IN_ 128
#define D_H_  256
#define D_OUT_ 128

#define PAD0_ 102400
#define TOT_  128000
#define SBLK_ 125

// ---- scratch (allocation-free rule: __device__ globals) ----
__device__ float g_h[(size_t)N1_ * D_H_];
__device__ int g_deg[TOT_];
__device__ int g_scan[TOT_];
__device__ int g_bsum[SBLK_];
__device__ int g_off[TOT_];
__device__ int g_wcur[TOT_];
__device__ int g_csr0[E0_];
__device__ int g_csr1[E1_];
__device__ __align__(128) __nv_bfloat16 g_A1h[(size_t)N1_ * 256];
__device__ __align__(128) __nv_bfloat16 g_A1l[(size_t)N1_ * 256];
__device__ __align__(128) __nv_bfloat16 g_A2h[(size_t)N2_ * 512];
__device__ __align__(128) __nv_bfloat16 g_A2l[(size_t)N2_ * 512];
__device__ __align__(128) __nv_bfloat16 g_B1h[256 * 256];
__device__ __align__(128) __nv_bfloat16 g_B1l[256 * 256];
__device__ __align__(128) __nv_bfloat16 g_B2h[128 * 512];
__device__ __align__(128) __nv_bfloat16 g_B2l[128 * 512];

// ---------------- ptx helpers (compute_103-safe) ----------------
__device__ __forceinline__ uint32_t smem_u32(const void* p) {
    uint32_t a;
    asm("{ .reg .u64 t; cvta.to.shared.u64 t, %1; cvt.u32.u64 %0, t; }" : "=r"(a) : "l"(p));
    return a;
}
__device__ __forceinline__ uint32_t sw128(uint32_t off) {
    return off ^ ((off >> 3) & 0x70);
}
__device__ __forceinline__ void cp16(uint32_t dst, const void* src, bool pred) {
    int sz = pred ? 16 : 0;
    asm volatile("cp.async.cg.shared.global [%0], [%1], 16, %2;"
                 :: "r"(dst), "l"(src), "r"(sz) : "memory");
}
__device__ __forceinline__ void ldsm4(uint32_t& r0, uint32_t& r1, uint32_t& r2, uint32_t& r3,
                                      uint32_t addr) {
    asm volatile("ldmatrix.sync.aligned.m8n8.x4.shared.b16 {%0,%1,%2,%3}, [%4];"
                 : "=r"(r0), "=r"(r1), "=r"(r2), "=r"(r3) : "r"(addr));
}
__device__ __forceinline__ void mma16816(float* c, uint32_t a0, uint32_t a1, uint32_t a2,
                                         uint32_t a3, uint32_t b0, uint32_t b1) {
    asm volatile(
        "mma.sync.aligned.m16n8k16.row.col.f32.bf16.bf16.f32 "
        "{%0,%1,%2,%3}, {%4,%5,%6,%7}, {%8,%9}, {%0,%1,%2,%3};"
        : "+f"(c[0]), "+f"(c[1]), "+f"(c[2]), "+f"(c[3])
        : "r"(a0), "r"(a1), "r"(a2), "r"(a3), "r"(b0), "r"(b1));
}
__device__ __forceinline__ uint32_t pack_bf16x2(float a, float b) {
    __nv_bfloat162 p = __floats2bfloat162_rn(a, b);
    return *(uint32_t*)&p;
}
__device__ __forceinline__ void split_store(__nv_bfloat16* hi, __nv_bfloat16* lo,
                                            size_t o, float4 v) {
    float hx = __bfloat162float(__float2bfloat16(v.x));
    float hy = __bfloat162float(__float2bfloat16(v.y));
    float hz = __bfloat162float(__float2bfloat16(v.z));
    float hw = __bfloat162float(__float2bfloat16(v.w));
    uint2 ph = make_uint2(pack_bf16x2(hx, hy), pack_bf16x2(hz, hw));
    uint2 pl = make_uint2(pack_bf16x2(v.x - hx, v.y - hy),
                          pack_bf16x2(v.z - hz, v.w - hw));
    *(uint2*)(hi + o) = ph;
    *(uint2*)(lo + o) = pl;
}

// ---------------- prep: zero degree array + split both weight matrices ----------------
__global__ void prep_kernel(int4* deg,
                            const float* __restrict__ Wl0, const float* __restrict__ Wr0,
                            const float* __restrict__ Wl1, const float* __restrict__ Wr1,
                            __nv_bfloat16* __restrict__ B1h, __nv_bfloat16* __restrict__ B1l,
                            __nv_bfloat16* __restrict__ B2h, __nv_bfloat16* __restrict__ B2l) {
    const int Z = TOT_ / 4;
    const int T1 = 256 * (256 / 4);
    const int T2 = 128 * (512 / 4);
    int i = blockIdx.x * blockDim.x + threadIdx.x;
    if (i < Z) {
        deg[i] = make_int4(0, 0, 0, 0);
    } else if (i < Z + T1) {
        int k = i - Z;
        int row = k / 64;
        int c4 = (k % 64) * 4;
        float4 v = (c4 < 128) ? *(const float4*)(Wl0 + (size_t)row * 128 + c4)
                              : *(const float4*)(Wr0 + (size_t)row * 128 + (c4 - 128));
        split_store(B1h, B1l, (size_t)row * 256 + c4, v);
    } else if (i < Z + T1 + T2) {
        int k = i - Z - T1;
        int row = k / 128;
        int c4 = (k % 128) * 4;
        float4 v = (c4 < 256) ? *(const float4*)(Wl1 + (size_t)row * 256 + c4)
                              : *(const float4*)(Wr1 + (size_t)row * 256 + (c4 - 256));
        split_store(B2h, B2l, (size_t)row * 512 + c4, v);
    }
}

// ---------------- CSR build kernels ----------------
__global__ void hist_deg(const int* __restrict__ d0, const int* __restrict__ d1,
                         int* __restrict__ deg) {
    int i = blockIdx.x * blockDim.x + threadIdx.x;
    if (i < E0_) atomicAdd(&deg[d0[i]], 1);
    else if (i < E0_ + E1_) atomicAdd(&deg[PAD0_ + d1[i - E0_]], 1);
}

__global__ void __launch_bounds__(1024) scan_part(const int* __restrict__ deg,
                                                  int* __restrict__ scn,
                                                  int* __restrict__ bsum) {
    __shared__ int sm[1024];
    int t = threadIdx.x;
    int gid = blockIdx.x * 1024 + t;
    sm[t] = deg[gid];
    __syncthreads();
    #pragma unroll
    for (int o = 1; o < 1024; o <<= 1) {
        int u = (t >= o) ? sm[t - o] : 0;
        __syncthreads();
        sm[t] += u;
        __syncthreads();
    }
    scn[gid] = sm[t];
    if (t == 1023) bsum[blockIdx.x] = sm[t];
}

// scan_add with block-sum prefix folded in (each CTA reduces bsum[0..b-1] itself)
__global__ void scan_add(const int* __restrict__ scn, const int* __restrict__ deg,
                         const int* __restrict__ bsum,
                         int* __restrict__ off, int* __restrict__ wcur) {
    __shared__ int sbase;
    int b = (blockIdx.x * 256) >> 10;   // uniform per CTA (256 divides 1024)
    if (threadIdx.x == 0) sbase = 0;
    __syncthreads();
    if (threadIdx.x < b) atomicAdd(&sbase, bsum[threadIdx.x]);
    __syncthreads();
    int gid = blockIdx.x * 256 + threadIdx.x;
    int incl = scn[gid] + sbase;
    int start = incl - deg[gid];
    if (gid >= PAD0_) start -= E0_;
    off[gid] = start;
    wcur[gid] = start;
}

__global__ void fill_csr(const int* __restrict__ s0, const int* __restrict__ d0,
                         const int* __restrict__ s1, const int* __restrict__ d1,
                         int* __restrict__ wcur,
                         int* __restrict__ csr0, int* __restrict__ csr1) {
    int i = blockIdx.x * blockDim.x + threadIdx.x;
    if (i < E0_) {
        int pos = atomicAdd(&wcur[d0[i]], 1);
        csr0[pos] = s0[i];
    } else if (i < E0_ + E1_) {
        int j = i - E0_;
        int pos = atomicAdd(&wcur[PAD0_ + d1[j]], 1);
        csr1[pos] = s1[j];
    }
}

// ---------------- atomic-free gather + mean + bf16 split ----------------
__global__ void __launch_bounds__(256) gather0(const float* __restrict__ x,
                                               const int* __restrict__ off,
                                               const int* __restrict__ csr,
                                               __nv_bfloat16* __restrict__ hi,
                                               __nv_bfloat16* __restrict__ lo) {
    int row = (blockIdx.x * blockDim.x + threadIdx.x) >> 5;
    int lane = threadIdx.x & 31;
    if (row >= N1_) return;
    int start = off[row];
    int deg = off[row + 1] - start;

    float4 acc = make_float4(0.f, 0.f, 0.f, 0.f);
    for (int base = 0; base < deg; base += 32) {
        int idx = 0;
        if (base + lane < deg) idx = __ldg(csr + start + base + lane);
        int nn = min(32, deg - base);
        #pragma unroll 4
        for (int j = 0; j < nn; j++) {
            int s = __shfl_sync(0xffffffffu, idx, j);
            float4 v = __ldg((const float4*)(x + (size_t)s * D_IN_) + lane);
            acc.x += v.x; acc.y += v.y; acc.z += v.z; acc.w += v.w;
        }
    }
    float inv = 1.0f / fmaxf((float)deg, 1.0f);
    acc.x *= inv; acc.y *= inv; acc.z *= inv; acc.w *= inv;
    size_t ro = (size_t)row * 256 + lane * 4;
    split_store(hi, lo, ro, acc);
    float4 xr = __ldg((const float4*)(x + (size_t)row * D_IN_) + lane);
    split_store(hi, lo, ro + 128, xr);
}

__global__ void __launch_bounds__(256) gather1(const float* __restrict__ h,
                                               const int* __restrict__ off,
                                               const int* __restrict__ csr,
                                               __nv_bfloat16* __restrict__ hi,
                                               __nv_bfloat16* __restrict__ lo) {
    int row = (blockIdx.x * blockDim.x + threadIdx.x) >> 5;
    int lane = threadIdx.x & 31;
    if (row >= N2_) return;
    int start = off[PAD0_ + row];
    int deg = off[PAD0_ + row + 1] - start;

    float4 a0 = make_float4(0.f, 0.f, 0.f, 0.f);
    float4 a1 = make_float4(0.f, 0.f, 0.f, 0.f);
    for (int base = 0; base < deg; base += 32) {
        int idx = 0;
        if (base + lane < deg) idx = __ldg(csr + start + base + lane);
        int nn = min(32, deg - base);
        #pragma unroll 2
        for (int j = 0; j < nn; j++) {
            int s = __shfl_sync(0xffffffffu, idx, j);
            const float4* hr = (const float4*)(h + (size_t)s * D_H_);
            float4 v0 = __ldg(hr + lane);
            float4 v1 = __ldg(hr + 32 + lane);
            a0.x += v0.x; a0.y += v0.y; a0.z += v0.z; a0.w += v0.w;
            a1.x += v1.x; a1.y += v1.y; a1.z += v1.z; a1.w += v1.w;
        }
    }
    float inv = 1.0f / fmaxf((float)deg, 1.0f);
    a0.x *= inv; a0.y *= inv; a0.z *= inv; a0.w *= inv;
    a1.x *= inv; a1.y *= inv; a1.z *= inv; a1.w *= inv;
    size_t ro = (size_t)row * 512 + lane * 4;
    split_store(hi, lo, ro, a0);
    split_store(hi, lo, ro + 128, a1);
}

// ---------------- mma.sync bf16 GEMM (R13 champion): 3-stage, MTILE x 128, 2 CTAs/SM ----------------
template<int K, int MTILE, bool RELU, bool WSPLIT>
__global__ void __launch_bounds__(256, 2)
gemm_mma(const __nv_bfloat16* __restrict__ Ah, const __nv_bfloat16* __restrict__ Al,
         const __nv_bfloat16* __restrict__ Bh, const __nv_bfloat16* __restrict__ Bl,
         const float* __restrict__ bias, float* __restrict__ C, int M, int Nstride,
         __nv_bfloat16* __restrict__ A2h, __nv_bfloat16* __restrict__ A2l, int n2) {
    constexpr int STAGES = 3;
    constexpr int KC = 64;
    constexpr int NCP = K / KC;
    constexpr int NCHUNK = 3 * NCP;
    constexpr int ATILE = MTILE * 128;
    constexpr int BTILE = 128 * 128;
    constexpr int STILE = ATILE + BTILE;
    constexpr int MT = MTILE / 32;
    constexpr int NT = 4;
    constexpr int AG = MTILE * 8;
    constexpr int NG = (AG + 1024) / 256;

    extern __shared__ char dsm[];
    char* tb = (char*)((((uintptr_t)dsm) + 1023) & ~(uintptr_t)1023);
    uint32_t aBase[STAGES], bBase[STAGES];
    #pragma unroll
    for (int s = 0; s < STAGES; s++) {
        aBase[s] = smem_u32(tb + s * STILE);
        bBase[s] = smem_u32(tb + s * STILE + ATILE);
    }

    const int tid  = threadIdx.x;
    const int wid  = tid >> 5;
    const int lane = tid & 31;
    const int bn0  = blockIdx.x * 128;
    const int m0   = blockIdx.y * MTILE;
    const int wm0  = (wid >> 2) * (MTILE / 2);
    const int wn0  = (wid & 3) * 32;

    float acc[MT][NT][4];
    #pragma unroll
    for (int i = 0; i < MT; i++)
        #pragma unroll
        for (int j = 0; j < NT; j++)
            #pragma unroll
            for (int e = 0; e < 4; e++) acc[i][j][e] = 0.f;

    auto load_chunk = [&](int ch, int buf) {
        const int pass = ch / NCP;
        const int kc = (ch % NCP) * KC;
        const __nv_bfloat16* As = (pass < 2) ? Ah : Al;
        const __nv_bfloat16* Bs = (pass == 1) ? Bl : Bh;
        #pragma unroll
        for (int it = 0; it < NG; it++) {
            int g = tid + it * 256;
            if (g < AG) {
                int row = g >> 3, c = g & 7;
                int gr = m0 + row;
                bool ok = gr < M;
                int grs = ok ? gr : (M - 1);
                cp16(aBase[buf] + sw128((uint32_t)(row * 128 + c * 16)),
                     As + (size_t)grs * K + kc + c * 8, ok);
            } else {
                int g2 = g - AG;
                int row = g2 >> 3, c = g2 & 7;
                cp16(bBase[buf] + sw128((uint32_t)(row * 128 + c * 16)),
                     Bs + (size_t)(bn0 + row) * K + kc + c * 8, true);
            }
        }
        asm volatile("cp.async.commit_group;" ::: "memory");
    };

    #pragma unroll
    for (int s = 0; s < STAGES - 1; s++) load_chunk(s, s);

    for (int ch = 0; ch < NCHUNK; ch++) {
        const int buf = ch % STAGES;
        if (ch == NCHUNK - 1)
            asm volatile("cp.async.wait_group 0;" ::: "memory");
        else
            asm volatile("cp.async.wait_group %0;" :: "n"(STAGES - 2) : "memory");
        __syncthreads();
        int nx = ch + STAGES - 1;
        if (nx < NCHUNK) load_chunk(nx, nx % STAGES);

        const uint32_t aB = aBase[buf];
        const uint32_t bB = bBase[buf];
        #pragma unroll
        for (int ks = 0; ks < 4; ks++) {
            const int kb = ks * 32;
            uint32_t bf[NT][2];
            #pragma unroll
            for (int nt2 = 0; nt2 < NT / 2; nt2++) {
                int n0 = wn0 + nt2 * 16;
                int rsel = (lane & 7) + ((lane >> 4) << 3);
                int ksel = (lane >> 3) & 1;
                uint32_t off = (uint32_t)((n0 + rsel) * 128 + kb + ksel * 16);
                ldsm4(bf[2 * nt2][0], bf[2 * nt2][1],
                      bf[2 * nt2 + 1][0], bf[2 * nt2 + 1][1], bB + sw128(off));
            }
            #pragma unroll
            for (int mt = 0; mt < MT; mt++) {
                int mrow = wm0 + mt * 16;
                int rsel = (lane & 7) + (((lane >> 3) & 1) << 3);
                int ksel = lane >> 4;
                uint32_t off = (uint32_t)((mrow + rsel) * 128 + kb + ksel * 16);
                uint32_t a0, a1, a2, a3;
                ldsm4(a0, a1, a2, a3, aB + sw128(off));
                #pragma unroll
                for (int nt = 0; nt < NT; nt++)
                    mma16816(acc[mt][nt], a0, a1, a2, a3, bf[nt][0], bf[nt][1]);
            }
        }
    }

    // epilogue
    #pragma unroll
    for (int mt = 0; mt < MT; mt++) {
        int rr[2];
        rr[0] = m0 + wm0 + mt * 16 + (lane >> 2);
        rr[1] = rr[0] + 8;
        #pragma unroll
        for (int nt = 0; nt < NT; nt++) {
            int c = bn0 + wn0 + nt * 8 + (lane & 3) * 2;
            float2 bv = *(const float2*)(bias + c);
            #pragma unroll
            for (int half = 0; half < 2; half++) {
                int r = rr[half];
                if (r < M) {
                    float2 v = make_float2(acc[mt][nt][2 * half + 0] + bv.x,
                                           acc[mt][nt][2 * half + 1] + bv.y);
                    if (RELU) { v.x = fmaxf(v.x, 0.f); v.y = fmaxf(v.y, 0.f); }
                    *(float2*)(C + (size_t)r * Nstride + c) = v;
                    if (WSPLIT && r < n2) {
                        float hx = __bfloat162float(__float2bfloat16(v.x));
                        float hy = __bfloat162float(__float2bfloat16(v.y));
                        size_t o = (size_t)r * 512 + 256 + c;
                        *(uint32_t*)(A2h + o) = pack_bf16x2(hx, hy);
                        *(uint32_t*)(A2l + o) = pack_bf16x2(v.x - hx, v.y - hy);
                    }
                }
            }
        }
    }
}

// ---------------- host side ----------------
extern "C" void kernel_launch(void* const* d_in, const int* in_sizes, int n_in,
                              void* d_out, int out_size) {
    const float* x   = (const float*)d_in[0];
    const float* Wl0 = (const float*)d_in[1];
    const float* bl0 = (const float*)d_in[2];
    const float* Wr0 = (const float*)d_in[3];
    const float* Wl1 = (const float*)d_in[4];
    const float* bl1 = (const float*)d_in[5];
    const float* Wr1 = (const float*)d_in[6];
    const int* e0s = (const int*)d_in[7];
    const int* e0d = (const int*)d_in[8];
    const int* e1s = (const int*)d_in[9];
    const int* e1d = (const int*)d_in[10];
    float* out = (float*)d_out;

    float* h;
    int *deg, *scn, *bsum, *off, *wcur, *csr0, *csr1;
    __nv_bfloat16 *A1h, *A1l, *A2h, *A2l, *B1h, *B1l, *B2h, *B2l;
    cudaGetSymbolAddress((void**)&h,    g_h);
    cudaGetSymbolAddress((void**)&deg,  g_deg);
    cudaGetSymbolAddress((void**)&scn,  g_scan);
    cudaGetSymbolAddress((void**)&bsum, g_bsum);
    cudaGetSymbolAddress((void**)&off,  g_off);
    cudaGetSymbolAddress((void**)&wcur, g_wcur);
    cudaGetSymbolAddress((void**)&csr0, g_csr0);
    cudaGetSymbolAddress((void**)&csr1, g_csr1);
    cudaGetSymbolAddress((void**)&A1h, g_A1h);
    cudaGetSymbolAddress((void**)&A1l, g_A1l);
    cudaGetSymbolAddress((void**)&A2h, g_A2h);
    cudaGetSymbolAddress((void**)&A2l, g_A2l);
    cudaGetSymbolAddress((void**)&B1h, g_B1h);
    cudaGetSymbolAddress((void**)&B1l, g_B1l);
    cudaGetSymbolAddress((void**)&B2h, g_B2h);
    cudaGetSymbolAddress((void**)&B2l, g_B2l);

    const int smem1 = 1024 + 3 * (128 * 128 + 128 * 128);  // 99328
    const int smem2 = 1024 + 3 * (64 * 128 + 128 * 128);   // 74752
    cudaFuncSetAttribute(gemm_mma<256, 128, true, true>,
                         cudaFuncAttributeMaxDynamicSharedMemorySize, smem1);
    cudaFuncSetAttribute(gemm_mma<512, 64, false, false>,
                         cudaFuncAttributeMaxDynamicSharedMemorySize, smem2);

    const int ET = E0_ + E1_;

    // prep: zero deg + weight splits (one launch)
    {
        int tot = TOT_ / 4 + 256 * 64 + 128 * 128;
        prep_kernel<<<(tot + 255) / 256, 256>>>((int4*)deg, Wl0, Wr0, Wl1, Wr1,
                                                B1h, B1l, B2h, B2l);
    }
    // CSR build (scan_top folded into scan_add)
    hist_deg<<<(ET + 255) / 256, 256>>>(e0d, e1d, deg);
    scan_part<<<SBLK_, 1024>>>(deg, scn, bsum);
    scan_add<<<TOT_ / 256, 256>>>(scn, deg, bsum, off, wcur);
    fill_csr<<<(ET + 255) / 256, 256>>>(e0s, e0d, e1s, e1d, wcur, csr0, csr1);

    // hop 0: gather + mean + split -> A1 (both halves)
    gather0<<<(N1_ * 32 + 255) / 256, 256>>>(x, off, csr0, A1h, A1l);

    // h = relu(A1 @ B1^T + bl0); epilogue emits A2 right half (h[:N2])
    {
        dim3 grid(2, (N1_ + 127) / 128);
        gemm_mma<256, 128, true, true><<<grid, 256, smem1>>>(
            A1h, A1l, B1h, B1l, bl0, h, N1_, 256, A2h, A2l, N2_);
    }

    // hop 1: gather + mean + split -> A2 left half
    gather1<<<(N2_ * 32 + 255) / 256, 256>>>(h, off, csr1, A2h, A2l);

    // out = A2 @ B2^T + bl1 (MTILE=64 -> 391 CTAs, shorter tail)
    {
        dim3 grid(1, (N2_ + 63) / 64);
        gemm_mma<512, 64, false, false><<<grid, 256, smem2>>>(
            A2h, A2l, B2h, B2l, bl1, out, N2_, 128, (__nv_bfloat16*)nullptr,
            (__nv_bfloat16*)nullptr, 0);
    }
}

// round 16
// speedup vs baseline: 1.2610x; 1.1300x over previous
#include <cuda_runtime.h>
#include <cuda_bf16.h>
#include <cuda_fp16.h>
#include <cstdint>

#define N0_   500000
#define N1_   100000
#define N2_   25000
#define E0_   1600000
#define E1_   400000
#define D_IN_ 128
#define D_H_  256
#define D_OUT_ 128

#define PAD0_ 102400
#define TOT_  128000
#define SBLK_ 125

// ---- scratch (allocation-free rule: __device__ globals) ----
__device__ float g_h[(size_t)N1_ * D_H_];
__device__ int g_deg[TOT_];
__device__ int g_scan[TOT_];
__device__ int g_bsum[SBLK_];
__device__ int g_off[TOT_];
__device__ int g_wcur[TOT_];
__device__ int g_csr0[E0_];
__device__ int g_csr1[E1_];
// gemm1 operands: A1 single fp16 plane; B1 fp16 hi/lo (exact split)
__device__ __align__(128) __half g_A1[(size_t)N1_ * 256];
__device__ __align__(128) __half g_B1h[256 * 256];
__device__ __align__(128) __half g_B1l[256 * 256];
// gemm2 operands: bf16 hi/lo (3-pass, full precision path)
__device__ __align__(128) __nv_bfloat16 g_A2h[(size_t)N2_ * 512];
__device__ __align__(128) __nv_bfloat16 g_A2l[(size_t)N2_ * 512];
__device__ __align__(128) __nv_bfloat16 g_B2h[128 * 512];
__device__ __align__(128) __nv_bfloat16 g_B2l[128 * 512];

// ---------------- ptx helpers (compute_103-safe) ----------------
__device__ __forceinline__ uint32_t smem_u32(const void* p) {
    uint32_t a;
    asm("{ .reg .u64 t; cvta.to.shared.u64 t, %1; cvt.u32.u64 %0, t; }" : "=r"(a) : "l"(p));
    return a;
}
__device__ __forceinline__ uint32_t sw128(uint32_t off) {
    return off ^ ((off >> 3) & 0x70);
}
__device__ __forceinline__ void cp16(uint32_t dst, const void* src, bool pred) {
    int sz = pred ? 16 : 0;
    asm volatile("cp.async.cg.shared.global [%0], [%1], 16, %2;"
                 :: "r"(dst), "l"(src), "r"(sz) : "memory");
}
__device__ __forceinline__ void ldsm4(uint32_t& r0, uint32_t& r1, uint32_t& r2, uint32_t& r3,
                                      uint32_t addr) {
    asm volatile("ldmatrix.sync.aligned.m8n8.x4.shared.b16 {%0,%1,%2,%3}, [%4];"
                 : "=r"(r0), "=r"(r1), "=r"(r2), "=r"(r3) : "r"(addr));
}
__device__ __forceinline__ void mma_bf16(float* c, uint32_t a0, uint32_t a1, uint32_t a2,
                                         uint32_t a3, uint32_t b0, uint32_t b1) {
    asm volatile(
        "mma.sync.aligned.m16n8k16.row.col.f32.bf16.bf16.f32 "
        "{%0,%1,%2,%3}, {%4,%5,%6,%7}, {%8,%9}, {%0,%1,%2,%3};"
        : "+f"(c[0]), "+f"(c[1]), "+f"(c[2]), "+f"(c[3])
        : "r"(a0), "r"(a1), "r"(a2), "r"(a3), "r"(b0), "r"(b1));
}
__device__ __forceinline__ void mma_f16(float* c, uint32_t a0, uint32_t a1, uint32_t a2,
                                        uint32_t a3, uint32_t b0, uint32_t b1) {
    asm volatile(
        "mma.sync.aligned.m16n8k16.row.col.f32.f16.f16.f32 "
        "{%0,%1,%2,%3}, {%4,%5,%6,%7}, {%8,%9}, {%0,%1,%2,%3};"
        : "+f"(c[0]), "+f"(c[1]), "+f"(c[2]), "+f"(c[3])
        : "r"(a0), "r"(a1), "r"(a2), "r"(a3), "r"(b0), "r"(b1));
}
__device__ __forceinline__ uint32_t pack_bf16x2(float a, float b) {
    __nv_bfloat162 p = __floats2bfloat162_rn(a, b);
    return *(uint32_t*)&p;
}
// bf16 hi/lo split store (full-precision path)
__device__ __forceinline__ void split_store(__nv_bfloat16* hi, __nv_bfloat16* lo,
                                            size_t o, float4 v) {
    float hx = __bfloat162float(__float2bfloat16(v.x));
    float hy = __bfloat162float(__float2bfloat16(v.y));
    float hz = __bfloat162float(__float2bfloat16(v.z));
    float hw = __bfloat162float(__float2bfloat16(v.w));
    uint2 ph = make_uint2(pack_bf16x2(hx, hy), pack_bf16x2(hz, hw));
    uint2 pl = make_uint2(pack_bf16x2(v.x - hx, v.y - hy),
                          pack_bf16x2(v.z - hz, v.w - hw));
    *(uint2*)(hi + o) = ph;
    *(uint2*)(lo + o) = pl;
}
// single fp16 store of 4 floats
__device__ __forceinline__ void store4_h(__half* p, size_t o, float4 v) {
    __half2 a = __floats2half2_rn(v.x, v.y);
    __half2 b = __floats2half2_rn(v.z, v.w);
    *(uint2*)(p + o) = make_uint2(*(uint32_t*)&a, *(uint32_t*)&b);
}
// fp16 hi/lo split store (for B1 weights; exact to ~2^-22)
__device__ __forceinline__ void split_store_h(__half* hi, __half* lo, size_t o, float4 v) {
    __half hx = __float2half_rn(v.x), hy = __float2half_rn(v.y);
    __half hz = __float2half_rn(v.z), hw = __float2half_rn(v.w);
    __half lx = __float2half_rn(v.x - __half2float(hx));
    __half ly = __float2half_rn(v.y - __half2float(hy));
    __half lz = __float2half_rn(v.z - __half2float(hz));
    __half lw = __float2half_rn(v.w - __half2float(hw));
    __half2 h0 = __halves2half2(hx, hy), h1 = __halves2half2(hz, hw);
    __half2 l0 = __halves2half2(lx, ly), l1 = __halves2half2(lz, lw);
    *(uint2*)(hi + o) = make_uint2(*(uint32_t*)&h0, *(uint32_t*)&h1);
    *(uint2*)(lo + o) = make_uint2(*(uint32_t*)&l0, *(uint32_t*)&l1);
}

// ---------------- prep: zero degree array + split both weight matrices ----------------
__global__ void prep_kernel(int4* deg,
                            const float* __restrict__ Wl0, const float* __restrict__ Wr0,
                            const float* __restrict__ Wl1, const float* __restrict__ Wr1,
                            __half* __restrict__ B1h, __half* __restrict__ B1l,
                            __nv_bfloat16* __restrict__ B2h, __nv_bfloat16* __restrict__ B2l) {
    const int Z = TOT_ / 4;
    const int T1 = 256 * (256 / 4);
    const int T2 = 128 * (512 / 4);
    int i = blockIdx.x * blockDim.x + threadIdx.x;
    if (i < Z) {
        deg[i] = make_int4(0, 0, 0, 0);
    } else if (i < Z + T1) {
        int k = i - Z;
        int row = k / 64;
        int c4 = (k % 64) * 4;
        float4 v = (c4 < 128) ? *(const float4*)(Wl0 + (size_t)row * 128 + c4)
                              : *(const float4*)(Wr0 + (size_t)row * 128 + (c4 - 128));
        split_store_h(B1h, B1l, (size_t)row * 256 + c4, v);
    } else if (i < Z + T1 + T2) {
        int k = i - Z - T1;
        int row = k / 128;
        int c4 = (k % 128) * 4;
        float4 v = (c4 < 256) ? *(const float4*)(Wl1 + (size_t)row * 256 + c4)
                              : *(const float4*)(Wr1 + (size_t)row * 256 + (c4 - 256));
        split_store(B2h, B2l, (size_t)row * 512 + c4, v);
    }
}

// ---------------- CSR build kernels ----------------
__global__ void hist_deg(const int* __restrict__ d0, const int* __restrict__ d1,
                         int* __restrict__ deg) {
    int i = blockIdx.x * blockDim.x + threadIdx.x;
    if (i < E0_) atomicAdd(&deg[d0[i]], 1);
    else if (i < E0_ + E1_) atomicAdd(&deg[PAD0_ + d1[i - E0_]], 1);
}

__global__ void __launch_bounds__(1024) scan_part(const int* __restrict__ deg,
                                                  int* __restrict__ scn,
                                                  int* __restrict__ bsum) {
    __shared__ int sm[1024];
    int t = threadIdx.x;
    int gid = blockIdx.x * 1024 + t;
    sm[t] = deg[gid];
    __syncthreads();
    #pragma unroll
    for (int o = 1; o < 1024; o <<= 1) {
        int u = (t >= o) ? sm[t - o] : 0;
        __syncthreads();
        sm[t] += u;
        __syncthreads();
    }
    scn[gid] = sm[t];
    if (t == 1023) bsum[blockIdx.x] = sm[t];
}

// scan_add with block-sum prefix folded in
__global__ void scan_add(const int* __restrict__ scn, const int* __restrict__ deg,
                         const int* __restrict__ bsum,
                         int* __restrict__ off, int* __restrict__ wcur) {
    __shared__ int sbase;
    int b = (blockIdx.x * 256) >> 10;
    if (threadIdx.x == 0) sbase = 0;
    __syncthreads();
    if (threadIdx.x < b) atomicAdd(&sbase, bsum[threadIdx.x]);
    __syncthreads();
    int gid = blockIdx.x * 256 + threadIdx.x;
    int incl = scn[gid] + sbase;
    int start = incl - deg[gid];
    if (gid >= PAD0_) start -= E0_;
    off[gid] = start;
    wcur[gid] = start;
}

__global__ void fill_csr(const int* __restrict__ s0, const int* __restrict__ d0,
                         const int* __restrict__ s1, const int* __restrict__ d1,
                         int* __restrict__ wcur,
                         int* __restrict__ csr0, int* __restrict__ csr1) {
    int i = blockIdx.x * blockDim.x + threadIdx.x;
    if (i < E0_) {
        int pos = atomicAdd(&wcur[d0[i]], 1);
        csr0[pos] = s0[i];
    } else if (i < E0_ + E1_) {
        int j = i - E0_;
        int pos = atomicAdd(&wcur[PAD0_ + d1[j]], 1);
        csr1[pos] = s1[j];
    }
}

// ---------------- atomic-free gather + mean ----------------
// hop 0: emits A1 (single fp16 plane, row stride 256)
__global__ void __launch_bounds__(256) gather0(const float* __restrict__ x,
                                               const int* __restrict__ off,
                                               const int* __restrict__ csr,
                                               __half* __restrict__ A1) {
    int row = (blockIdx.x * blockDim.x + threadIdx.x) >> 5;
    int lane = threadIdx.x & 31;
    if (row >= N1_) return;
    int start = off[row];
    int deg = off[row + 1] - start;

    float4 acc = make_float4(0.f, 0.f, 0.f, 0.f);
    for (int base = 0; base < deg; base += 32) {
        int idx = 0;
        if (base + lane < deg) idx = __ldg(csr + start + base + lane);
        int nn = min(32, deg - base);
        #pragma unroll 4
        for (int j = 0; j < nn; j++) {
            int s = __shfl_sync(0xffffffffu, idx, j);
            float4 v = __ldg((const float4*)(x + (size_t)s * D_IN_) + lane);
            acc.x += v.x; acc.y += v.y; acc.z += v.z; acc.w += v.w;
        }
    }
    float inv = 1.0f / fmaxf((float)deg, 1.0f);
    acc.x *= inv; acc.y *= inv; acc.z *= inv; acc.w *= inv;
    size_t ro = (size_t)row * 256 + lane * 4;
    store4_h(A1, ro, acc);
    float4 xr = __ldg((const float4*)(x + (size_t)row * D_IN_) + lane);
    store4_h(A1, ro + 128, xr);
}

// hop 1: reads fp32 h, emits A2 left half in bf16 hi/lo (stride 512)
__global__ void __launch_bounds__(256) gather1(const float* __restrict__ h,
                                               const int* __restrict__ off,
                                               const int* __restrict__ csr,
                                               __nv_bfloat16* __restrict__ hi,
                                               __nv_bfloat16* __restrict__ lo) {
    int row = (blockIdx.x * blockDim.x + threadIdx.x) >> 5;
    int lane = threadIdx.x & 31;
    if (row >= N2_) return;
    int start = off[PAD0_ + row];
    int deg = off[PAD0_ + row + 1] - start;

    float4 a0 = make_float4(0.f, 0.f, 0.f, 0.f);
    float4 a1 = make_float4(0.f, 0.f, 0.f, 0.f);
    for (int base = 0; base < deg; base += 32) {
        int idx = 0;
        if (base + lane < deg) idx = __ldg(csr + start + base + lane);
        int nn = min(32, deg - base);
        #pragma unroll 2
        for (int j = 0; j < nn; j++) {
            int s = __shfl_sync(0xffffffffu, idx, j);
            const float4* hr = (const float4*)(h + (size_t)s * D_H_);
            float4 v0 = __ldg(hr + lane);
            float4 v1 = __ldg(hr + 32 + lane);
            a0.x += v0.x; a0.y += v0.y; a0.z += v0.z; a0.w += v0.w;
            a1.x += v1.x; a1.y += v1.y; a1.z += v1.z; a1.w += v1.w;
        }
    }
    float inv = 1.0f / fmaxf((float)deg, 1.0f);
    a0.x *= inv; a0.y *= inv; a0.z *= inv; a0.w *= inv;
    a1.x *= inv; a1.y *= inv; a1.z *= inv; a1.w *= inv;
    size_t ro = (size_t)row * 512 + lane * 4;
    split_store(hi, lo, ro, a0);
    split_store(hi, lo, ro + 128, a1);
}

// ---------------- gemm1: fp16 2-pass (A single plane; B = Bh + Bl exact split) ----------------
// h = relu(A @ (Bh+Bl)^T + bias). 3-stage pipeline, 128x128 tiles, 2 CTAs/SM.
// WSPLIT epilogue emits A2 right half (bf16 hi/lo, stride 512) for rows < n2.
__global__ void __launch_bounds__(256, 2)
gemm_f16(const __half* __restrict__ A,
         const __half* __restrict__ Bh, const __half* __restrict__ Bl,
         const float* __restrict__ bias, float* __restrict__ C, int M,
         __nv_bfloat16* __restrict__ A2h, __nv_bfloat16* __restrict__ A2l, int n2) {
    constexpr int K = 256;
    constexpr int STAGES = 3;
    constexpr int KC = 64;
    constexpr int NCP = K / KC;              // 4
    constexpr int NCHUNK = 2 * NCP;          // 8 (two passes)
    constexpr int ATILE = 128 * 128;
    constexpr int BTILE = 128 * 128;
    constexpr int STILE = ATILE + BTILE;
    constexpr int MT = 4;
    constexpr int NT = 4;
    constexpr int NG = 2048 / 256;

    extern __shared__ char dsm[];
    char* tb = (char*)((((uintptr_t)dsm) + 1023) & ~(uintptr_t)1023);
    uint32_t aBase[STAGES], bBase[STAGES];
    #pragma unroll
    for (int s = 0; s < STAGES; s++) {
        aBase[s] = smem_u32(tb + s * STILE);
        bBase[s] = smem_u32(tb + s * STILE + ATILE);
    }

    const int tid  = threadIdx.x;
    const int wid  = tid >> 5;
    const int lane = tid & 31;
    const int bn0  = blockIdx.x * 128;
    const int m0   = blockIdx.y * 128;
    const int wm0  = (wid >> 2) * 64;
    const int wn0  = (wid & 3) * 32;

    float acc[MT][NT][4];
    #pragma unroll
    for (int i = 0; i < MT; i++)
        #pragma unroll
        for (int j = 0; j < NT; j++)
            #pragma unroll
            for (int e = 0; e < 4; e++) acc[i][j][e] = 0.f;

    auto load_chunk = [&](int ch, int buf) {
        const int pass = ch / NCP;
        const int kc = (ch % NCP) * KC;
        const __half* Bs = pass ? Bl : Bh;
        #pragma unroll
        for (int it = 0; it < NG; it++) {
            int g = tid + it * 256;
            if (g < 1024) {
                int row = g >> 3, c = g & 7;
                int gr = m0 + row;
                bool ok = gr < M;
                int grs = ok ? gr : (M - 1);
                cp16(aBase[buf] + sw128((uint32_t)(row * 128 + c * 16)),
                     A + (size_t)grs * K + kc + c * 8, ok);
            } else {
                int g2 = g - 1024;
                int row = g2 >> 3, c = g2 & 7;
                cp16(bBase[buf] + sw128((uint32_t)(row * 128 + c * 16)),
                     Bs + (size_t)(bn0 + row) * K + kc + c * 8, true);
            }
        }
        asm volatile("cp.async.commit_group;" ::: "memory");
    };

    #pragma unroll
    for (int s = 0; s < STAGES - 1; s++) load_chunk(s, s);

    for (int ch = 0; ch < NCHUNK; ch++) {
        const int buf = ch % STAGES;
        if (ch == NCHUNK - 1)
            asm volatile("cp.async.wait_group 0;" ::: "memory");
        else
            asm volatile("cp.async.wait_group %0;" :: "n"(STAGES - 2) : "memory");
        __syncthreads();
        int nx = ch + STAGES - 1;
        if (nx < NCHUNK) load_chunk(nx, nx % STAGES);

        const uint32_t aB = aBase[buf];
        const uint32_t bB = bBase[buf];
        #pragma unroll
        for (int ks = 0; ks < 4; ks++) {
            const int kb = ks * 32;
            uint32_t bf[NT][2];
            #pragma unroll
            for (int nt2 = 0; nt2 < NT / 2; nt2++) {
                int n0 = wn0 + nt2 * 16;
                int rsel = (lane & 7) + ((lane >> 4) << 3);
                int ksel = (lane >> 3) & 1;
                uint32_t off = (uint32_t)((n0 + rsel) * 128 + kb + ksel * 16);
                ldsm4(bf[2 * nt2][0], bf[2 * nt2][1],
                      bf[2 * nt2 + 1][0], bf[2 * nt2 + 1][1], bB + sw128(off));
            }
            #pragma unroll
            for (int mt = 0; mt < MT; mt++) {
                int mrow = wm0 + mt * 16;
                int rsel = (lane & 7) + (((lane >> 3) & 1) << 3);
                int ksel = lane >> 4;
                uint32_t off = (uint32_t)((mrow + rsel) * 128 + kb + ksel * 16);
                uint32_t a0, a1, a2, a3;
                ldsm4(a0, a1, a2, a3, aB + sw128(off));
                #pragma unroll
                for (int nt = 0; nt < NT; nt++)
                    mma_f16(acc[mt][nt], a0, a1, a2, a3, bf[nt][0], bf[nt][1]);
            }
        }
    }

    // epilogue: bias + relu, fp32 C, optional A2 right-half bf16 hi/lo
    #pragma unroll
    for (int mt = 0; mt < MT; mt++) {
        int rr[2];
        rr[0] = m0 + wm0 + mt * 16 + (lane >> 2);
        rr[1] = rr[0] + 8;
        #pragma unroll
        for (int nt = 0; nt < NT; nt++) {
            int c = bn0 + wn0 + nt * 8 + (lane & 3) * 2;
            float2 bv = *(const float2*)(bias + c);
            #pragma unroll
            for (int half = 0; half < 2; half++) {
                int r = rr[half];
                if (r < M) {
                    float2 v = make_float2(acc[mt][nt][2 * half + 0] + bv.x,
                                           acc[mt][nt][2 * half + 1] + bv.y);
                    v.x = fmaxf(v.x, 0.f); v.y = fmaxf(v.y, 0.f);
                    *(float2*)(C + (size_t)r * 256 + c) = v;
                    if (r < n2) {
                        float hx = __bfloat162float(__float2bfloat16(v.x));
                        float hy = __bfloat162float(__float2bfloat16(v.y));
                        size_t o = (size_t)r * 512 + 256 + c;
                        *(uint32_t*)(A2h + o) = pack_bf16x2(hx, hy);
                        *(uint32_t*)(A2l + o) = pack_bf16x2(v.x - hx, v.y - hy);
                    }
                }
            }
        }
    }
}

// ---------------- gemm2: bf16 3-pass (R13 champion, MTILE=64) ----------------
template<int K, int MTILE>
__global__ void __launch_bounds__(256, 2)
gemm_bf16(const __nv_bfloat16* __restrict__ Ah, const __nv_bfloat16* __restrict__ Al,
          const __nv_bfloat16* __restrict__ Bh, const __nv_bfloat16* __restrict__ Bl,
          const float* __restrict__ bias, float* __restrict__ C, int M, int Nstride) {
    constexpr int STAGES = 3;
    constexpr int KC = 64;
    constexpr int NCP = K / KC;
    constexpr int NCHUNK = 3 * NCP;
    constexpr int ATILE = MTILE * 128;
    constexpr int BTILE = 128 * 128;
    constexpr int STILE = ATILE + BTILE;
    constexpr int MT = MTILE / 32;
    constexpr int NT = 4;
    constexpr int AG = MTILE * 8;
    constexpr int NG = (AG + 1024) / 256;

    extern __shared__ char dsm[];
    char* tb = (char*)((((uintptr_t)dsm) + 1023) & ~(uintptr_t)1023);
    uint32_t aBase[STAGES], bBase[STAGES];
    #pragma unroll
    for (int s = 0; s < STAGES; s++) {
        aBase[s] = smem_u32(tb + s * STILE);
        bBase[s] = smem_u32(tb + s * STILE + ATILE);
    }

    const int tid  = threadIdx.x;
    const int wid  = tid >> 5;
    const int lane = tid & 31;
    const int bn0  = blockIdx.x * 128;
    const int m0   = blockIdx.y * MTILE;
    const int wm0  = (wid >> 2) * (MTILE / 2);
    const int wn0  = (wid & 3) * 32;

    float acc[MT][NT][4];
    #pragma unroll
    for (int i = 0; i < MT; i++)
        #pragma unroll
        for (int j = 0; j < NT; j++)
            #pragma unroll
            for (int e = 0; e < 4; e++) acc[i][j][e] = 0.f;

    auto load_chunk = [&](int ch, int buf) {
        const int pass = ch / NCP;
        const int kc = (ch % NCP) * KC;
        const __nv_bfloat16* As = (pass < 2) ? Ah : Al;
        const __nv_bfloat16* Bs = (pass == 1) ? Bl : Bh;
        #pragma unroll
        for (int it = 0; it < NG; it++) {
            int g = tid + it * 256;
            if (g < AG) {
                int row = g >> 3, c = g & 7;
                int gr = m0 + row;
                bool ok = gr < M;
                int grs = ok ? gr : (M - 1);
                cp16(aBase[buf] + sw128((uint32_t)(row * 128 + c * 16)),
                     As + (size_t)grs * K + kc + c * 8, ok);
            } else {
                int g2 = g - AG;
                int row = g2 >> 3, c = g2 & 7;
                cp16(bBase[buf] + sw128((uint32_t)(row * 128 + c * 16)),
                     Bs + (size_t)(bn0 + row) * K + kc + c * 8, true);
            }
        }
        asm volatile("cp.async.commit_group;" ::: "memory");
    };

    #pragma unroll
    for (int s = 0; s < STAGES - 1; s++) load_chunk(s, s);

    for (int ch = 0; ch < NCHUNK; ch++) {
        const int buf = ch % STAGES;
        if (ch == NCHUNK - 1)
            asm volatile("cp.async.wait_group 0;" ::: "memory");
        else
            asm volatile("cp.async.wait_group %0;" :: "n"(STAGES - 2) : "memory");
        __syncthreads();
        int nx = ch + STAGES - 1;
        if (nx < NCHUNK) load_chunk(nx, nx % STAGES);

        const uint32_t aB = aBase[buf];
        const uint32_t bB = bBase[buf];
        #pragma unroll
        for (int ks = 0; ks < 4; ks++) {
            const int kb = ks * 32;
            uint32_t bf[NT][2];
            #pragma unroll
            for (int nt2 = 0; nt2 < NT / 2; nt2++) {
                int n0 = wn0 + nt2 * 16;
                int rsel = (lane & 7) + ((lane >> 4) << 3);
                int ksel = (lane >> 3) & 1;
                uint32_t off = (uint32_t)((n0 + rsel) * 128 + kb + ksel * 16);
                ldsm4(bf[2 * nt2][0], bf[2 * nt2][1],
                      bf[2 * nt2 + 1][0], bf[2 * nt2 + 1][1], bB + sw128(off));
            }
            #pragma unroll
            for (int mt = 0; mt < MT; mt++) {
                int mrow = wm0 + mt * 16;
                int rsel = (lane & 7) + (((lane >> 3) & 1) << 3);
                int ksel = lane >> 4;
                uint32_t off = (uint32_t)((mrow + rsel) * 128 + kb + ksel * 16);
                uint32_t a0, a1, a2, a3;
                ldsm4(a0, a1, a2, a3, aB + sw128(off));
                #pragma unroll
                for (int nt = 0; nt < NT; nt++)
                    mma_bf16(acc[mt][nt], a0, a1, a2, a3, bf[nt][0], bf[nt][1]);
            }
        }
    }

    // epilogue
    #pragma unroll
    for (int mt = 0; mt < MT; mt++) {
        int rr[2];
        rr[0] = m0 + wm0 + mt * 16 + (lane >> 2);
        rr[1] = rr[0] + 8;
        #pragma unroll
        for (int nt = 0; nt < NT; nt++) {
            int c = bn0 + wn0 + nt * 8 + (lane & 3) * 2;
            float2 bv = *(const float2*)(bias + c);
            #pragma unroll
            for (int half = 0; half < 2; half++) {
                int r = rr[half];
                if (r < M) {
                    float2 v = make_float2(acc[mt][nt][2 * half + 0] + bv.x,
                                           acc[mt][nt][2 * half + 1] + bv.y);
                    *(float2*)(C + (size_t)r * Nstride + c) = v;
                }
            }
        }
    }
}

// ---------------- host side ----------------
extern "C" void kernel_launch(void* const* d_in, const int* in_sizes, int n_in,
                              void* d_out, int out_size) {
    const float* x   = (const float*)d_in[0];
    const float* Wl0 = (const float*)d_in[1];
    const float* bl0 = (const float*)d_in[2];
    const float* Wr0 = (const float*)d_in[3];
    const float* Wl1 = (const float*)d_in[4];
    const float* bl1 = (const float*)d_in[5];
    const float* Wr1 = (const float*)d_in[6];
    const int* e0s = (const int*)d_in[7];
    const int* e0d = (const int*)d_in[8];
    const int* e1s = (const int*)d_in[9];
    const int* e1d = (const int*)d_in[10];
    float* out = (float*)d_out;

    float* h;
    int *deg, *scn, *bsum, *off, *wcur, *csr0, *csr1;
    __half *A1, *B1h, *B1l;
    __nv_bfloat16 *A2h, *A2l, *B2h, *B2l;
    cudaGetSymbolAddress((void**)&h,    g_h);
    cudaGetSymbolAddress((void**)&deg,  g_deg);
    cudaGetSymbolAddress((void**)&scn,  g_scan);
    cudaGetSymbolAddress((void**)&bsum, g_bsum);
    cudaGetSymbolAddress((void**)&off,  g_off);
    cudaGetSymbolAddress((void**)&wcur, g_wcur);
    cudaGetSymbolAddress((void**)&csr0, g_csr0);
    cudaGetSymbolAddress((void**)&csr1, g_csr1);
    cudaGetSymbolAddress((void**)&A1,  g_A1);
    cudaGetSymbolAddress((void**)&B1h, g_B1h);
    cudaGetSymbolAddress((void**)&B1l, g_B1l);
    cudaGetSymbolAddress((void**)&A2h, g_A2h);
    cudaGetSymbolAddress((void**)&A2l, g_A2l);
    cudaGetSymbolAddress((void**)&B2h, g_B2h);
    cudaGetSymbolAddress((void**)&B2l, g_B2l);

    const int smem1 = 1024 + 3 * (128 * 128 + 128 * 128);  // 99328
    const int smem2 = 1024 + 3 * (64 * 128 + 128 * 128);   // 74752
    cudaFuncSetAttribute(gemm_f16,
                         cudaFuncAttributeMaxDynamicSharedMemorySize, smem1);
    cudaFuncSetAttribute(gemm_bf16<512, 64>,
                         cudaFuncAttributeMaxDynamicSharedMemorySize, smem2);

    const int ET = E0_ + E1_;

    // prep: zero deg + weight splits (one launch)
    {
        int tot = TOT_ / 4 + 256 * 64 + 128 * 128;
        prep_kernel<<<(tot + 255) / 256, 256>>>((int4*)deg, Wl0, Wr0, Wl1, Wr1,
                                                B1h, B1l, B2h, B2l);
    }
    // CSR build
    hist_deg<<<(ET + 255) / 256, 256>>>(e0d, e1d, deg);
    scan_part<<<SBLK_, 1024>>>(deg, scn, bsum);
    scan_add<<<TOT_ / 256, 256>>>(scn, deg, bsum, off, wcur);
    fill_csr<<<(ET + 255) / 256, 256>>>(e0s, e0d, e1s, e1d, wcur, csr0, csr1);

    // hop 0: gather + mean -> A1 (fp16)
    gather0<<<(N1_ * 32 + 255) / 256, 256>>>(x, off, csr0, A1);

    // h = relu(A1 @ (B1h+B1l)^T + bl0); epilogue emits A2 right half
    {
        dim3 grid(2, (N1_ + 127) / 128);
        gemm_f16<<<grid, 256, smem1>>>(A1, B1h, B1l, bl0, h, N1_, A2h, A2l, N2_);
    }

    // hop 1: gather + mean + bf16 split -> A2 left half
    gather1<<<(N2_ * 32 + 255) / 256, 256>>>(h, off, csr1, A2h, A2l);

    // out = A2 @ B2^T + bl1 (bf16 3-pass)
    {
        dim3 grid(1, (N2_ + 63) / 64);
        gemm_bf16<512, 64><<<grid, 256, smem2>>>(
            A2h, A2l, B2h, B2l, bl1, out, N2_, 128);
    }
}

// round 17
// speedup vs baseline: 1.5031x; 1.1920x over previous
#include <cuda_runtime.h>
#include <cuda_bf16.h>
#include <cuda_fp16.h>
#include <cstdint>

#define N0_   500000
#define N1_   100000
#define N2_   25000
#define E0_   1600000
#define E1_   400000
#define D_IN_ 128
#define D_H_  256
#define D_OUT_ 128

#define PAD0_ 102400
#define TOT_  128000
#define SBLK_ 125

// ---- scratch (allocation-free rule: __device__ globals) ----
__device__ float g_h[(size_t)N1_ * D_H_];
__device__ int g_deg[TOT_];
__device__ int g_scan[TOT_];
__device__ int g_bsum[SBLK_];
__device__ int g_off[TOT_];
__device__ int g_wcur[TOT_];
__device__ int g_csr0[E0_];
__device__ int g_csr1[E1_];
// gemm1: A1, B1 single fp16 planes (1-pass)
__device__ __align__(128) __half g_A1[(size_t)N1_ * 256];
__device__ __align__(128) __half g_B1[256 * 256];
// gemm2: A2 single fp16 plane; B2 fp16 hi/lo (2-pass)
__device__ __align__(128) __half g_A2[(size_t)N2_ * 512];
__device__ __align__(128) __half g_B2h[128 * 512];
__device__ __align__(128) __half g_B2l[128 * 512];

// ---------------- ptx helpers (compute_103-safe) ----------------
__device__ __forceinline__ uint32_t smem_u32(const void* p) {
    uint32_t a;
    asm("{ .reg .u64 t; cvta.to.shared.u64 t, %1; cvt.u32.u64 %0, t; }" : "=r"(a) : "l"(p));
    return a;
}
__device__ __forceinline__ uint32_t sw128(uint32_t off) {
    return off ^ ((off >> 3) & 0x70);
}
__device__ __forceinline__ void cp16(uint32_t dst, const void* src, bool pred) {
    int sz = pred ? 16 : 0;
    asm volatile("cp.async.cg.shared.global [%0], [%1], 16, %2;"
                 :: "r"(dst), "l"(src), "r"(sz) : "memory");
}
__device__ __forceinline__ void ldsm4(uint32_t& r0, uint32_t& r1, uint32_t& r2, uint32_t& r3,
                                      uint32_t addr) {
    asm volatile("ldmatrix.sync.aligned.m8n8.x4.shared.b16 {%0,%1,%2,%3}, [%4];"
                 : "=r"(r0), "=r"(r1), "=r"(r2), "=r"(r3) : "r"(addr));
}
__device__ __forceinline__ void mma_f16(float* c, uint32_t a0, uint32_t a1, uint32_t a2,
                                        uint32_t a3, uint32_t b0, uint32_t b1) {
    asm volatile(
        "mma.sync.aligned.m16n8k16.row.col.f32.f16.f16.f32 "
        "{%0,%1,%2,%3}, {%4,%5,%6,%7}, {%8,%9}, {%0,%1,%2,%3};"
        : "+f"(c[0]), "+f"(c[1]), "+f"(c[2]), "+f"(c[3])
        : "r"(a0), "r"(a1), "r"(a2), "r"(a3), "r"(b0), "r"(b1));
}
__device__ __forceinline__ uint32_t pack_h2(float a, float b) {
    __half2 p = __floats2half2_rn(a, b);
    return *(uint32_t*)&p;
}
// single fp16 store of 4 floats
__device__ __forceinline__ void store4_h(__half* p, size_t o, float4 v) {
    *(uint2*)(p + o) = make_uint2(pack_h2(v.x, v.y), pack_h2(v.z, v.w));
}
// fp16 hi/lo split store (exact to ~2^-22)
__device__ __forceinline__ void split_store_h(__half* hi, __half* lo, size_t o, float4 v) {
    __half hx = __float2half_rn(v.x), hy = __float2half_rn(v.y);
    __half hz = __float2half_rn(v.z), hw = __float2half_rn(v.w);
    float lx = v.x - __half2float(hx), ly = v.y - __half2float(hy);
    float lz = v.z - __half2float(hz), lw = v.w - __half2float(hw);
    __half2 h0 = __halves2half2(hx, hy), h1 = __halves2half2(hz, hw);
    *(uint2*)(hi + o) = make_uint2(*(uint32_t*)&h0, *(uint32_t*)&h1);
    *(uint2*)(lo + o) = make_uint2(pack_h2(lx, ly), pack_h2(lz, lw));
}

// ---------------- prep: zero degree array + split both weight matrices ----------------
__global__ void prep_kernel(int4* deg,
                            const float* __restrict__ Wl0, const float* __restrict__ Wr0,
                            const float* __restrict__ Wl1, const float* __restrict__ Wr1,
                            __half* __restrict__ B1,
                            __half* __restrict__ B2h, __half* __restrict__ B2l) {
    const int Z = TOT_ / 4;
    const int T1 = 256 * (256 / 4);
    const int T2 = 128 * (512 / 4);
    int i = blockIdx.x * blockDim.x + threadIdx.x;
    if (i < Z) {
        deg[i] = make_int4(0, 0, 0, 0);
    } else if (i < Z + T1) {
        int k = i - Z;
        int row = k / 64;
        int c4 = (k % 64) * 4;
        float4 v = (c4 < 128) ? *(const float4*)(Wl0 + (size_t)row * 128 + c4)
                              : *(const float4*)(Wr0 + (size_t)row * 128 + (c4 - 128));
        store4_h(B1, (size_t)row * 256 + c4, v);
    } else if (i < Z + T1 + T2) {
        int k = i - Z - T1;
        int row = k / 128;
        int c4 = (k % 128) * 4;
        float4 v = (c4 < 256) ? *(const float4*)(Wl1 + (size_t)row * 256 + c4)
                              : *(const float4*)(Wr1 + (size_t)row * 256 + (c4 - 256));
        split_store_h(B2h, B2l, (size_t)row * 512 + c4, v);
    }
}

// ---------------- CSR build kernels ----------------
__global__ void hist_deg(const int* __restrict__ d0, const int* __restrict__ d1,
                         int* __restrict__ deg) {
    int i = blockIdx.x * blockDim.x + threadIdx.x;
    if (i < E0_) atomicAdd(&deg[d0[i]], 1);
    else if (i < E0_ + E1_) atomicAdd(&deg[PAD0_ + d1[i - E0_]], 1);
}

__global__ void __launch_bounds__(1024) scan_part(const int* __restrict__ deg,
                                                  int* __restrict__ scn,
                                                  int* __restrict__ bsum) {
    __shared__ int sm[1024];
    int t = threadIdx.x;
    int gid = blockIdx.x * 1024 + t;
    sm[t] = deg[gid];
    __syncthreads();
    #pragma unroll
    for (int o = 1; o < 1024; o <<= 1) {
        int u = (t >= o) ? sm[t - o] : 0;
        __syncthreads();
        sm[t] += u;
        __syncthreads();
    }
    scn[gid] = sm[t];
    if (t == 1023) bsum[blockIdx.x] = sm[t];
}

__global__ void scan_add(const int* __restrict__ scn, const int* __restrict__ deg,
                         const int* __restrict__ bsum,
                         int* __restrict__ off, int* __restrict__ wcur) {
    __shared__ int sbase;
    int b = (blockIdx.x * 256) >> 10;
    if (threadIdx.x == 0) sbase = 0;
    __syncthreads();
    if (threadIdx.x < b) atomicAdd(&sbase, bsum[threadIdx.x]);
    __syncthreads();
    int gid = blockIdx.x * 256 + threadIdx.x;
    int incl = scn[gid] + sbase;
    int start = incl - deg[gid];
    if (gid >= PAD0_) start -= E0_;
    off[gid] = start;
    wcur[gid] = start;
}

__global__ void fill_csr(const int* __restrict__ s0, const int* __restrict__ d0,
                         const int* __restrict__ s1, const int* __restrict__ d1,
                         int* __restrict__ wcur,
                         int* __restrict__ csr0, int* __restrict__ csr1) {
    int i = blockIdx.x * blockDim.x + threadIdx.x;
    if (i < E0_) {
        int pos = atomicAdd(&wcur[d0[i]], 1);
        csr0[pos] = s0[i];
    } else if (i < E0_ + E1_) {
        int j = i - E0_;
        int pos = atomicAdd(&wcur[PAD0_ + d1[j]], 1);
        csr1[pos] = s1[j];
    }
}

// ---------------- atomic-free gather + mean ----------------
__global__ void __launch_bounds__(256) gather0(const float* __restrict__ x,
                                               const int* __restrict__ off,
                                               const int* __restrict__ csr,
                                               __half* __restrict__ A1) {
    int row = (blockIdx.x * blockDim.x + threadIdx.x) >> 5;
    int lane = threadIdx.x & 31;
    if (row >= N1_) return;
    int start = off[row];
    int deg = off[row + 1] - start;

    float4 acc = make_float4(0.f, 0.f, 0.f, 0.f);
    for (int base = 0; base < deg; base += 32) {
        int idx = 0;
        if (base + lane < deg) idx = __ldg(csr + start + base + lane);
        int nn = min(32, deg - base);
        #pragma unroll 4
        for (int j = 0; j < nn; j++) {
            int s = __shfl_sync(0xffffffffu, idx, j);
            float4 v = __ldg((const float4*)(x + (size_t)s * D_IN_) + lane);
            acc.x += v.x; acc.y += v.y; acc.z += v.z; acc.w += v.w;
        }
    }
    float inv = 1.0f / fmaxf((float)deg, 1.0f);
    acc.x *= inv; acc.y *= inv; acc.z *= inv; acc.w *= inv;
    size_t ro = (size_t)row * 256 + lane * 4;
    store4_h(A1, ro, acc);
    float4 xr = __ldg((const float4*)(x + (size_t)row * D_IN_) + lane);
    store4_h(A1, ro + 128, xr);
}

// hop 1: reads fp32 h, emits A2 left half as single fp16 (stride 512)
__global__ void __launch_bounds__(256) gather1(const float* __restrict__ h,
                                               const int* __restrict__ off,
                                               const int* __restrict__ csr,
                                               __half* __restrict__ A2) {
    int row = (blockIdx.x * blockDim.x + threadIdx.x) >> 5;
    int lane = threadIdx.x & 31;
    if (row >= N2_) return;
    int start = off[PAD0_ + row];
    int deg = off[PAD0_ + row + 1] - start;

    float4 a0 = make_float4(0.f, 0.f, 0.f, 0.f);
    float4 a1 = make_float4(0.f, 0.f, 0.f, 0.f);
    for (int base = 0; base < deg; base += 32) {
        int idx = 0;
        if (base + lane < deg) idx = __ldg(csr + start + base + lane);
        int nn = min(32, deg - base);
        #pragma unroll 2
        for (int j = 0; j < nn; j++) {
            int s = __shfl_sync(0xffffffffu, idx, j);
            const float4* hr = (const float4*)(h + (size_t)s * D_H_);
            float4 v0 = __ldg(hr + lane);
            float4 v1 = __ldg(hr + 32 + lane);
            a0.x += v0.x; a0.y += v0.y; a0.z += v0.z; a0.w += v0.w;
            a1.x += v1.x; a1.y += v1.y; a1.z += v1.z; a1.w += v1.w;
        }
    }
    float inv = 1.0f / fmaxf((float)deg, 1.0f);
    a0.x *= inv; a0.y *= inv; a0.z *= inv; a0.w *= inv;
    a1.x *= inv; a1.y *= inv; a1.z *= inv; a1.w *= inv;
    size_t ro = (size_t)row * 512 + lane * 4;
    store4_h(A2, ro, a0);
    store4_h(A2, ro + 128, a1);
}

// ---------------- fp16 GEMM: NPASS passes over {B0, B1opt}, 3-stage, 2 CTAs/SM ----------------
// C[M, Nstride tile at bn0] = opt_relu( sum_p A @ Bp^T + bias ).
// WSPLIT: rows < n2 also emit fp16 into A2out at col offset 256, stride 512.
template<int K, int MTILE, int NPASS, bool RELU, bool WSPLIT>
__global__ void __launch_bounds__(256, 2)
gemm_f16(const __half* __restrict__ A,
         const __half* __restrict__ B0, const __half* __restrict__ B1p,
         const float* __restrict__ bias, float* __restrict__ C, int M, int Nstride,
         __half* __restrict__ A2out, int n2) {
    constexpr int STAGES = 3;
    constexpr int KC = 64;
    constexpr int NCP = K / KC;
    constexpr int NCHUNK = NPASS * NCP;
    constexpr int ATILE = MTILE * 128;
    constexpr int BTILE = 128 * 128;
    constexpr int STILE = ATILE + BTILE;
    constexpr int MT = MTILE / 32;
    constexpr int NT = 4;
    constexpr int AG = MTILE * 8;
    constexpr int NG = (AG + 1024) / 256;

    extern __shared__ char dsm[];
    char* tb = (char*)((((uintptr_t)dsm) + 1023) & ~(uintptr_t)1023);
    uint32_t aBase[STAGES], bBase[STAGES];
    #pragma unroll
    for (int s = 0; s < STAGES; s++) {
        aBase[s] = smem_u32(tb + s * STILE);
        bBase[s] = smem_u32(tb + s * STILE + ATILE);
    }

    const int tid  = threadIdx.x;
    const int wid  = tid >> 5;
    const int lane = tid & 31;
    const int bn0  = blockIdx.x * 128;
    const int m0   = blockIdx.y * MTILE;
    const int wm0  = (wid >> 2) * (MTILE / 2);
    const int wn0  = (wid & 3) * 32;

    float acc[MT][NT][4];
    #pragma unroll
    for (int i = 0; i < MT; i++)
        #pragma unroll
        for (int j = 0; j < NT; j++)
            #pragma unroll
            for (int e = 0; e < 4; e++) acc[i][j][e] = 0.f;

    auto load_chunk = [&](int ch, int buf) {
        const int pass = ch / NCP;
        const int kc = (ch % NCP) * KC;
        const __half* Bs = (NPASS == 1 || pass == 0) ? B0 : B1p;
        #pragma unroll
        for (int it = 0; it < NG; it++) {
            int g = tid + it * 256;
            if (g < AG) {
                int row = g >> 3, c = g & 7;
                int gr = m0 + row;
                bool ok = gr < M;
                int grs = ok ? gr : (M - 1);
                cp16(aBase[buf] + sw128((uint32_t)(row * 128 + c * 16)),
                     A + (size_t)grs * K + kc + c * 8, ok);
            } else {
                int g2 = g - AG;
                int row = g2 >> 3, c = g2 & 7;
                cp16(bBase[buf] + sw128((uint32_t)(row * 128 + c * 16)),
                     Bs + (size_t)(bn0 + row) * K + kc + c * 8, true);
            }
        }
        asm volatile("cp.async.commit_group;" ::: "memory");
    };

    #pragma unroll
    for (int s = 0; s < STAGES - 1; s++)
        if (s < NCHUNK) load_chunk(s, s);

    for (int ch = 0; ch < NCHUNK; ch++) {
        const int buf = ch % STAGES;
        if (ch == NCHUNK - 1)
            asm volatile("cp.async.wait_group 0;" ::: "memory");
        else if (ch + STAGES - 1 >= NCHUNK)
            asm volatile("cp.async.wait_group 0;" ::: "memory");
        else
            asm volatile("cp.async.wait_group %0;" :: "n"(STAGES - 2) : "memory");
        __syncthreads();
        int nx = ch + STAGES - 1;
        if (nx < NCHUNK) load_chunk(nx, nx % STAGES);

        const uint32_t aB = aBase[buf];
        const uint32_t bB = bBase[buf];
        #pragma unroll
        for (int ks = 0; ks < 4; ks++) {
            const int kb = ks * 32;
            uint32_t bf[NT][2];
            #pragma unroll
            for (int nt2 = 0; nt2 < NT / 2; nt2++) {
                int n0 = wn0 + nt2 * 16;
                int rsel = (lane & 7) + ((lane >> 4) << 3);
                int ksel = (lane >> 3) & 1;
                uint32_t off = (uint32_t)((n0 + rsel) * 128 + kb + ksel * 16);
                ldsm4(bf[2 * nt2][0], bf[2 * nt2][1],
                      bf[2 * nt2 + 1][0], bf[2 * nt2 + 1][1], bB + sw128(off));
            }
            #pragma unroll
            for (int mt = 0; mt < MT; mt++) {
                int mrow = wm0 + mt * 16;
                int rsel = (lane & 7) + (((lane >> 3) & 1) << 3);
                int ksel = lane >> 4;
                uint32_t off = (uint32_t)((mrow + rsel) * 128 + kb + ksel * 16);
                uint32_t a0, a1, a2, a3;
                ldsm4(a0, a1, a2, a3, aB + sw128(off));
                #pragma unroll
                for (int nt = 0; nt < NT; nt++)
                    mma_f16(acc[mt][nt], a0, a1, a2, a3, bf[nt][0], bf[nt][1]);
            }
        }
    }

    // epilogue
    #pragma unroll
    for (int mt = 0; mt < MT; mt++) {
        int rr[2];
        rr[0] = m0 + wm0 + mt * 16 + (lane >> 2);
        rr[1] = rr[0] + 8;
        #pragma unroll
        for (int nt = 0; nt < NT; nt++) {
            int c = bn0 + wn0 + nt * 8 + (lane & 3) * 2;
            float2 bv = *(const float2*)(bias + c);
            #pragma unroll
            for (int half = 0; half < 2; half++) {
                int r = rr[half];
                if (r < M) {
                    float2 v = make_float2(acc[mt][nt][2 * half + 0] + bv.x,
                                           acc[mt][nt][2 * half + 1] + bv.y);
                    if (RELU) { v.x = fmaxf(v.x, 0.f); v.y = fmaxf(v.y, 0.f); }
                    *(float2*)(C + (size_t)r * Nstride + c) = v;
                    if (WSPLIT && r < n2) {
                        *(uint32_t*)(A2out + (size_t)r * 512 + 256 + c) =
                            pack_h2(v.x, v.y);
                    }
                }
            }
        }
    }
}

// ---------------- host side ----------------
extern "C" void kernel_launch(void* const* d_in, const int* in_sizes, int n_in,
                              void* d_out, int out_size) {
    const float* x   = (const float*)d_in[0];
    const float* Wl0 = (const float*)d_in[1];
    const float* bl0 = (const float*)d_in[2];
    const float* Wr0 = (const float*)d_in[3];
    const float* Wl1 = (const float*)d_in[4];
    const float* bl1 = (const float*)d_in[5];
    const float* Wr1 = (const float*)d_in[6];
    const int* e0s = (const int*)d_in[7];
    const int* e0d = (const int*)d_in[8];
    const int* e1s = (const int*)d_in[9];
    const int* e1d = (const int*)d_in[10];
    float* out = (float*)d_out;

    float* h;
    int *deg, *scn, *bsum, *off, *wcur, *csr0, *csr1;
    __half *A1, *B1, *A2, *B2h, *B2l;
    cudaGetSymbolAddress((void**)&h,    g_h);
    cudaGetSymbolAddress((void**)&deg,  g_deg);
    cudaGetSymbolAddress((void**)&scn,  g_scan);
    cudaGetSymbolAddress((void**)&bsum, g_bsum);
    cudaGetSymbolAddress((void**)&off,  g_off);
    cudaGetSymbolAddress((void**)&wcur, g_wcur);
    cudaGetSymbolAddress((void**)&csr0, g_csr0);
    cudaGetSymbolAddress((void**)&csr1, g_csr1);
    cudaGetSymbolAddress((void**)&A1,  g_A1);
    cudaGetSymbolAddress((void**)&B1,  g_B1);
    cudaGetSymbolAddress((void**)&A2,  g_A2);
    cudaGetSymbolAddress((void**)&B2h, g_B2h);
    cudaGetSymbolAddress((void**)&B2l, g_B2l);

    const int smem1 = 1024 + 3 * (128 * 128 + 128 * 128);  // 99328
    const int smem2 = 1024 + 3 * (64 * 128 + 128 * 128);   // 74752
    cudaFuncSetAttribute((const void*)gemm_f16<256, 128, 1, true, true>,
                         cudaFuncAttributeMaxDynamicSharedMemorySize, smem1);
    cudaFuncSetAttribute((const void*)gemm_f16<512, 64, 2, false, false>,
                         cudaFuncAttributeMaxDynamicSharedMemorySize, smem2);

    const int ET = E0_ + E1_;

    // prep: zero deg + weight conversions (one launch)
    {
        int tot = TOT_ / 4 + 256 * 64 + 128 * 128;
        prep_kernel<<<(tot + 255) / 256, 256>>>((int4*)deg, Wl0, Wr0, Wl1, Wr1,
                                                B1, B2h, B2l);
    }
    // CSR build
    hist_deg<<<(ET + 255) / 256, 256>>>(e0d, e1d, deg);
    scan_part<<<SBLK_, 1024>>>(deg, scn, bsum);
    scan_add<<<TOT_ / 256, 256>>>(scn, deg, bsum, off, wcur);
    fill_csr<<<(ET + 255) / 256, 256>>>(e0s, e0d, e1s, e1d, wcur, csr0, csr1);

    // hop 0: gather + mean -> A1 (fp16)
    gather0<<<(N1_ * 32 + 255) / 256, 256>>>(x, off, csr0, A1);

    // h = relu(A1 @ B1^T + bl0); epilogue emits A2 right half (fp16)
    {
        dim3 grid(2, (N1_ + 127) / 128);
        gemm_f16<256, 128, 1, true, true><<<grid, 256, smem1>>>(
            A1, B1, (const __half*)nullptr, bl0, h, N1_, 256, A2, N2_);
    }

    // hop 1: gather + mean -> A2 left half (fp16)
    gather1<<<(N2_ * 32 + 255) / 256, 256>>>(h, off, csr1, A2);

    // out = A2 @ (B2h+B2l)^T + bl1 (2-pass fp16)
    {
        dim3 grid(1, (N2_ + 63) / 64);
        gemm_f16<512, 64, 2, false, false><<<grid, 256, smem2>>>(
            A2, B2h, B2l, bl1, out, N2_, 128, (__half*)nullptr, 0);
    }
}